// round 12
// baseline (speedup 1.0000x reference)
#include <cuda_runtime.h>
#include <math.h>

#define N 4096
#define D 512

// ---------------- scratch (static __device__, per harness rules) -------------
__device__ float  g_fn[(size_t)N * D];      // normalized features, TF32-rounded
__device__ float  g_sims[(size_t)N * N];    // sims2[q1][q2], both axes label-sorted
__device__ float  g_ls[N];                  // sorted labels
__device__ int    g_perm[N];                // perm[q] = original index
__device__ int    g_ipos[N];                // ipos[i]  = position of i in sorted order
__device__ double g_loss[N];                // per-row losses

__device__ __forceinline__ float tf32_round(float x) {
    unsigned r;
    asm("cvt.rna.tf32.f32 %0, %1;" : "=r"(r) : "f"(x));
    return __uint_as_float(r);
}

// m16n8k8 TF32 MMA, fp32 accumulate
__device__ __forceinline__ void mma_tf32(float* c, const unsigned* a, const unsigned* b) {
    asm volatile(
        "mma.sync.aligned.m16n8k8.row.col.f32.tf32.tf32.f32 "
        "{%0,%1,%2,%3}, {%4,%5,%6,%7}, {%8,%9}, {%0,%1,%2,%3};\n"
        : "+f"(c[0]), "+f"(c[1]), "+f"(c[2]), "+f"(c[3])
        : "r"(a[0]), "r"(a[1]), "r"(a[2]), "r"(a[3]), "r"(b[0]), "r"(b[1]));
}

// ---------------- 1) bitonic sort of labels (single block) -------------------
__global__ void sort_kernel(const float* __restrict__ labels) {
    __shared__ float key[N];
    __shared__ int   idx[N];
    int tid = threadIdx.x;  // 1024 threads
    for (int p = tid; p < N; p += 1024) { key[p] = labels[p]; idx[p] = p; }
    __syncthreads();
    for (int k = 2; k <= N; k <<= 1) {
        for (int j = k >> 1; j > 0; j >>= 1) {
            for (int p = tid; p < N; p += 1024) {
                int q = p ^ j;
                if (q > p) {
                    bool up = ((p & k) == 0);
                    float a = key[p], b = key[q];
                    bool swap = up ? (a > b || (a == b && idx[p] > idx[q]))
                                   : (a < b || (a == b && idx[p] < idx[q]));
                    if (swap) {
                        key[p] = b; key[q] = a;
                        int t2 = idx[p]; idx[p] = idx[q]; idx[q] = t2;
                    }
                }
            }
            __syncthreads();
        }
    }
    for (int p = tid; p < N; p += 1024) {
        g_ls[p] = key[p];
        g_perm[p] = idx[p];
        g_ipos[idx[p]] = p;
    }
}

// ---------------- 2) row normalization, output rounded to TF32 ---------------
__global__ void norm_kernel(const float* __restrict__ X) {
    int i = blockIdx.x, tid = threadIdx.x;  // 128 threads, 512 elems
    const float4* xr = (const float4*)(X + (size_t)i * D);
    float4 v = xr[tid];
    float ss = v.x * v.x + v.y * v.y + v.z * v.z + v.w * v.w;
    #pragma unroll
    for (int o = 16; o > 0; o >>= 1) ss += __shfl_xor_sync(0xffffffffu, ss, o);
    __shared__ float ws[4];
    if ((tid & 31) == 0) ws[tid >> 5] = ss;
    __syncthreads();
    float tot = ws[0] + ws[1] + ws[2] + ws[3];
    float nrm = sqrtf(tot);
    float4 o4 = make_float4(tf32_round(v.x / nrm), tf32_round(v.y / nrm),
                            tf32_round(v.z / nrm), tf32_round(v.w / nrm));
    ((float4*)g_fn)[(size_t)i * (D / 4) + tid] = o4;
}

// ---------------- 3) symmetric tensor-core GEMM + exp, cp.async 2-stage ------
// Same MMA/fragment order as R11 -> bitwise-identical sims; loads are now
// LDGSTS double-buffered so global latency overlaps MMA compute.
#define KT 32
#define NKT (D / KT)
__global__ __launch_bounds__(256) void gemm_mma_sym_kernel() {
    extern __shared__ float dyn[];
    float (*As)[128][36] = (float(*)[128][36])dyn;                 // 2 stages
    float (*Bs)[128][36] = (float(*)[128][36])(dyn + 2 * 128 * 36);
    int* permA = (int*)(dyn + 4 * 128 * 36);
    int* permB = permA + 128;

    int tid = threadIdx.x;
    int lane = tid & 31, wid = tid >> 5;
    int warp_m = wid & 3;    // 4 warps over 128 rows (32 each)
    int warp_n = wid >> 2;   // 2 warps over 128 cols (64 each)

    int bi = 0, bj = 0;
    {
        int r = blockIdx.x;
        #pragma unroll 1
        for (int b = 0; b < 32; b++) {
            int cnt = 32 - b;
            if (r < cnt) { bi = b; bj = b + r; break; }
            r -= cnt;
        }
    }
    if (tid < 128) permA[tid] = g_perm[bi * 128 + tid];
    else           permB[tid - 128] = g_perm[bj * 128 + (tid - 128)];
    __syncthreads();

    // per-thread load coords (fixed across tiles)
    int lrow[4], lc4[4];
    #pragma unroll
    for (int l = 0; l < 4; l++) {
        int j = tid + l * 256;
        lrow[l] = j >> 3;
        lc4[l]  = (j & 7) * 4;
    }

    float acc[2][8][4];
    #pragma unroll
    for (int mf = 0; mf < 2; mf++)
        #pragma unroll
        for (int nf = 0; nf < 8; nf++)
            #pragma unroll
            for (int r = 0; r < 4; r++) acc[mf][nf][r] = 0.0f;

    // prefetch tile 0 into stage 0
    #pragma unroll
    for (int l = 0; l < 4; l++) {
        unsigned da = (unsigned)__cvta_generic_to_shared(&As[0][lrow[l]][lc4[l]]);
        asm volatile("cp.async.cg.shared.global [%0], [%1], 16;\n"
                     :: "r"(da), "l"(&g_fn[(size_t)permA[lrow[l]] * D + lc4[l]]));
        unsigned db = (unsigned)__cvta_generic_to_shared(&Bs[0][lrow[l]][lc4[l]]);
        asm volatile("cp.async.cg.shared.global [%0], [%1], 16;\n"
                     :: "r"(db), "l"(&g_fn[(size_t)permB[lrow[l]] * D + lc4[l]]));
    }
    asm volatile("cp.async.commit_group;\n");

    int stage = 0;
    for (int ki = 0; ki < NKT; ki++) {
        asm volatile("cp.async.wait_group 0;\n");
        __syncthreads();
        if (ki + 1 < NKT) {
            int kt = (ki + 1) * KT;
            int ns = stage ^ 1;
            #pragma unroll
            for (int l = 0; l < 4; l++) {
                unsigned da = (unsigned)__cvta_generic_to_shared(&As[ns][lrow[l]][lc4[l]]);
                asm volatile("cp.async.cg.shared.global [%0], [%1], 16;\n"
                             :: "r"(da), "l"(&g_fn[(size_t)permA[lrow[l]] * D + kt + lc4[l]]));
                unsigned db = (unsigned)__cvta_generic_to_shared(&Bs[ns][lrow[l]][lc4[l]]);
                asm volatile("cp.async.cg.shared.global [%0], [%1], 16;\n"
                             :: "r"(db), "l"(&g_fn[(size_t)permB[lrow[l]] * D + kt + lc4[l]]));
            }
            asm volatile("cp.async.commit_group;\n");
        }
        #pragma unroll
        for (int ks = 0; ks < 4; ks++) {
            int k0 = ks * 8 + (lane & 3);
            unsigned a[2][4], b[8][2];
            #pragma unroll
            for (int mf = 0; mf < 2; mf++) {
                int m0 = warp_m * 32 + mf * 16 + (lane >> 2);
                a[mf][0] = __float_as_uint(As[stage][m0][k0]);
                a[mf][1] = __float_as_uint(As[stage][m0 + 8][k0]);
                a[mf][2] = __float_as_uint(As[stage][m0][k0 + 4]);
                a[mf][3] = __float_as_uint(As[stage][m0 + 8][k0 + 4]);
            }
            #pragma unroll
            for (int nf = 0; nf < 8; nf++) {
                int n0 = warp_n * 64 + nf * 8 + (lane >> 2);
                b[nf][0] = __float_as_uint(Bs[stage][n0][k0]);
                b[nf][1] = __float_as_uint(Bs[stage][n0][k0 + 4]);
            }
            #pragma unroll
            for (int mf = 0; mf < 2; mf++)
                #pragma unroll
                for (int nf = 0; nf < 8; nf++)
                    mma_tf32(acc[mf][nf], a[mf], b[nf]);
        }
        __syncthreads();
        stage ^= 1;
    }

    // exp epilogue in registers
    #pragma unroll
    for (int mf = 0; mf < 2; mf++)
        #pragma unroll
        for (int nf = 0; nf < 8; nf++)
            #pragma unroll
            for (int r = 0; r < 4; r++)
                acc[mf][nf][r] = expf(acc[mf][nf][r] / 0.07f);

    // direct writes
    #pragma unroll
    for (int mf = 0; mf < 2; mf++) {
        #pragma unroll
        for (int r = 0; r < 4; r++) {
            int row_local = warp_m * 32 + mf * 16 + (lane >> 2) + ((r >> 1) ? 8 : 0);
            int gq1 = bi * 128 + row_local;
            #pragma unroll
            for (int nf = 0; nf < 8; nf++) {
                int col_local = warp_n * 64 + nf * 8 + (lane & 3) * 2 + (r & 1);
                g_sims[(size_t)gq1 * N + bj * 128 + col_local] = acc[mf][nf][r];
            }
        }
    }

    // mirror write via transpose bounce (stage buffer aliases dyn)
    if (bi != bj) {
        float (*stg)[129] = (float(*)[129])dyn;
        #pragma unroll 1
        for (int cc = 0; cc < 4; cc++) {
            __syncthreads();
            if (warp_m == cc) {
                #pragma unroll
                for (int mf = 0; mf < 2; mf++) {
                    #pragma unroll
                    for (int r = 0; r < 4; r++) {
                        int rr = mf * 16 + (lane >> 2) + ((r >> 1) ? 8 : 0);
                        #pragma unroll
                        for (int nf = 0; nf < 8; nf++) {
                            int col_local = warp_n * 64 + nf * 8 + (lane & 3) * 2 + (r & 1);
                            stg[rr][col_local] = acc[mf][nf][r];
                        }
                    }
                }
            }
            __syncthreads();
            for (int j = tid; j < 32 * 128; j += 256) {
                int rr = j & 31, cp = j >> 5;
                g_sims[(size_t)(bj * 128 + cp) * N + bi * 128 + cc * 32 + rr] = stg[rr][cp];
            }
        }
    }
}

// ---------------- 4) fused per-row prefix scan + two-pointer loss terms ------
__global__ __launch_bounds__(512) void scan_terms_kernel() {
    extern __shared__ char dsm[];
    double* spref = (double*)dsm;                    // 32 KB
    float*  lsh   = (float*)(dsm + 32768);           // 16 KB
    double* red   = (double*)(dsm + 32768 + 16384);  // 4 KB
    __shared__ double warpsum[16];

    int q1 = blockIdx.x, tid = threadIdx.x;  // 512 threads
    const float* __restrict__ row = g_sims + (size_t)q1 * N;

    for (int p = tid; p < N; p += 512) lsh[p] = g_ls[p];

    // ---- prefix scan (bitwise-same arithmetic as R9-R11) -------------------
    const float4* r4 = (const float4*)row;
    float4 v0 = r4[tid * 2 + 0];
    float4 v1 = r4[tid * 2 + 1];
    double loc[8];
    double s = 0.0;
    s += (double)v0.x; loc[0] = s;
    s += (double)v0.y; loc[1] = s;
    s += (double)v0.z; loc[2] = s;
    s += (double)v0.w; loc[3] = s;
    s += (double)v1.x; loc[4] = s;
    s += (double)v1.y; loc[5] = s;
    s += (double)v1.z; loc[6] = s;
    s += (double)v1.w; loc[7] = s;

    double ws = s;
    #pragma unroll
    for (int o = 1; o < 32; o <<= 1) {
        double v = __shfl_up_sync(0xffffffffu, ws, o);
        if ((tid & 31) >= o) ws += v;
    }
    if ((tid & 31) == 31) warpsum[tid >> 5] = ws;
    __syncthreads();
    if (tid < 16) {
        double w = warpsum[tid];
        #pragma unroll
        for (int o = 1; o < 16; o <<= 1) {
            double v = __shfl_up_sync(0x0000ffffu, w, o);
            if (tid >= o) w += v;
        }
        warpsum[tid] = w;
    }
    __syncthreads();
    double offset = ws - s;  // exclusive within warp
    if (tid >= 32) offset += warpsum[(tid >> 5) - 1];
    int base = tid * 8;
    #pragma unroll
    for (int k = 0; k < 8; k++) spref[base + k] = loc[k] + offset;
    __syncthreads();

    // ---- terms: contiguous per-thread chunks, monotone two-pointer windows -
    const float li = lsh[q1];
    const int ipos = q1;
    const double selfsim = (double)__ldg(&row[ipos]);
    const double St = spref[N - 1] - selfsim;
    const double qt = rint(St * 8.0);

    const int pstart = tid * 8;
    const int pend = pstart + 8;
    double acc = 0.0;

    // LEFT side: p in [pstart, min(pend, ipos));  t decreasing as p increases
    {
        int pL_end = pend < ipos ? pend : ipos;
        if (pstart < pL_end) {
            int p = pstart;
            float t = fabsf(li - lsh[p]);
            int lo = 0, hi = p;                    // a = first q with dist <= t
            while (lo < hi) {
                int mid = (lo + hi) >> 1;
                if (fabsf(li - lsh[mid]) <= t) hi = mid; else lo = mid + 1;
            }
            int a = lo;
            lo = ipos; hi = N - 1;                 // b = last q with dist <= t
            while (lo < hi) {
                int mid = (lo + hi + 1) >> 1;
                if (fabsf(li - lsh[mid]) <= t) lo = mid; else hi = mid - 1;
            }
            int b = lo;
            for (;;) {
                double W  = spref[b] - (a > 0 ? spref[a - 1] : 0.0);
                double den = (qt - rint((W - selfsim) * 8.0)) * 0.125;
                if (den > 0.0) acc += (double)__ldg(&row[p]) / den;
                if (++p >= pL_end) break;
                t = fabsf(li - lsh[p]);
                while (fabsf(li - lsh[a]) > t) a++;   // stops at <= p
                while (fabsf(li - lsh[b]) > t) b--;   // stops at >= ipos
            }
        }
    }
    // RIGHT side: p in (ipos, pend);  t increasing as p increases
    {
        int pR_start = pstart > ipos + 1 ? pstart : ipos + 1;
        if (pR_start < pend) {
            int p = pR_start;
            float t = fabsf(li - lsh[p]);
            int lo = 0, hi = ipos;                 // a = first q with dist <= t
            while (lo < hi) {
                int mid = (lo + hi) >> 1;
                if (fabsf(li - lsh[mid]) <= t) hi = mid; else lo = mid + 1;
            }
            int a = lo;
            lo = ipos; hi = N - 1;                 // b = last q with dist <= t
            while (lo < hi) {
                int mid = (lo + hi + 1) >> 1;
                if (fabsf(li - lsh[mid]) <= t) lo = mid; else hi = mid - 1;
            }
            int b = lo;
            for (;;) {
                double W  = spref[b] - (a > 0 ? spref[a - 1] : 0.0);
                double den = (qt - rint((W - selfsim) * 8.0)) * 0.125;
                if (den > 0.0) acc += (double)__ldg(&row[p]) / den;
                if (++p >= pend) break;
                t = fabsf(li - lsh[p]);
                while (b + 1 < N && fabsf(li - lsh[b + 1]) <= t) b++;
                while (a > 0 && fabsf(li - lsh[a - 1]) <= t) a--;
            }
        }
    }

    red[tid] = acc;
    __syncthreads();
    for (int o = 256; o > 0; o >>= 1) {
        if (tid < o) red[tid] += red[tid + o];
        __syncthreads();
    }
    if (tid == 0) g_loss[q1] = red[0] / (double)(N - 1);
}

// ---------------- 5) deterministic final reduction ---------------------------
__global__ void final_reduce_kernel(float* __restrict__ out) {
    __shared__ double red[512];
    int tid = threadIdx.x;
    double s = 0.0;
    for (int k = tid; k < N; k += 512) s += g_loss[k];
    red[tid] = s;
    __syncthreads();
    for (int o = 256; o > 0; o >>= 1) {
        if (tid < o) red[tid] += red[tid + o];
        __syncthreads();
    }
    if (tid == 0) out[0] = (float)(red[0] / (double)N);
}

// ---------------- launcher ----------------------------------------------------
extern "C" void kernel_launch(void* const* d_in, const int* in_sizes, int n_in,
                              void* d_out, int out_size) {
    const float* features = (const float*)d_in[0];
    const float* labels   = (const float*)d_in[1];
    float* out = (float*)d_out;

    cudaFuncSetAttribute(gemm_mma_sym_kernel,
                         cudaFuncAttributeMaxDynamicSharedMemorySize, 74752);
    cudaFuncSetAttribute(scan_terms_kernel,
                         cudaFuncAttributeMaxDynamicSharedMemorySize, 53248);

    sort_kernel<<<1, 1024>>>(labels);
    norm_kernel<<<N, 128>>>(features);
    gemm_mma_sym_kernel<<<528, 256, 74752>>>();
    scan_terms_kernel<<<N, 512, 53248>>>();
    final_reduce_kernel<<<1, 512>>>(out);
}

// round 13
// speedup vs baseline: 1.4973x; 1.4973x over previous
#include <cuda_runtime.h>
#include <math.h>

#define N 4096
#define D 512

// ---------------- scratch (static __device__, per harness rules) -------------
__device__ float  g_fn[(size_t)N * D];      // normalized features, TF32-rounded
__device__ float  g_sims[(size_t)N * N];    // sims2[q1][q2], both axes label-sorted
__device__ float  g_ls[N];                  // sorted labels
__device__ int    g_perm[N];                // perm[q] = original index
__device__ int    g_ipos[N];                // ipos[i]  = position of i in sorted order
__device__ double g_loss[N];                // per-row losses

__device__ __forceinline__ float tf32_round(float x) {
    unsigned r;
    asm("cvt.rna.tf32.f32 %0, %1;" : "=r"(r) : "f"(x));
    return __uint_as_float(r);
}

// m16n8k8 TF32 MMA, fp32 accumulate
__device__ __forceinline__ void mma_tf32(float* c, const unsigned* a, const unsigned* b) {
    asm volatile(
        "mma.sync.aligned.m16n8k8.row.col.f32.tf32.tf32.f32 "
        "{%0,%1,%2,%3}, {%4,%5,%6,%7}, {%8,%9}, {%0,%1,%2,%3};\n"
        : "+f"(c[0]), "+f"(c[1]), "+f"(c[2]), "+f"(c[3])
        : "r"(a[0]), "r"(a[1]), "r"(a[2]), "r"(a[3]), "r"(b[0]), "r"(b[1]));
}

// ---------------- 1) bitonic sort of labels (single block) -------------------
__global__ void sort_kernel(const float* __restrict__ labels) {
    __shared__ float key[N];
    __shared__ int   idx[N];
    int tid = threadIdx.x;  // 1024 threads
    for (int p = tid; p < N; p += 1024) { key[p] = labels[p]; idx[p] = p; }
    __syncthreads();
    for (int k = 2; k <= N; k <<= 1) {
        for (int j = k >> 1; j > 0; j >>= 1) {
            for (int p = tid; p < N; p += 1024) {
                int q = p ^ j;
                if (q > p) {
                    bool up = ((p & k) == 0);
                    float a = key[p], b = key[q];
                    bool swap = up ? (a > b || (a == b && idx[p] > idx[q]))
                                   : (a < b || (a == b && idx[p] < idx[q]));
                    if (swap) {
                        key[p] = b; key[q] = a;
                        int t2 = idx[p]; idx[p] = idx[q]; idx[q] = t2;
                    }
                }
            }
            __syncthreads();
        }
    }
    for (int p = tid; p < N; p += 1024) {
        g_ls[p] = key[p];
        g_perm[p] = idx[p];
        g_ipos[idx[p]] = p;
    }
}

// ---------------- 2) row normalization, output rounded to TF32 ---------------
__global__ void norm_kernel(const float* __restrict__ X) {
    int i = blockIdx.x, tid = threadIdx.x;  // 128 threads, 512 elems
    const float4* xr = (const float4*)(X + (size_t)i * D);
    float4 v = xr[tid];
    float ss = v.x * v.x + v.y * v.y + v.z * v.z + v.w * v.w;
    #pragma unroll
    for (int o = 16; o > 0; o >>= 1) ss += __shfl_xor_sync(0xffffffffu, ss, o);
    __shared__ float ws[4];
    if ((tid & 31) == 0) ws[tid >> 5] = ss;
    __syncthreads();
    float tot = ws[0] + ws[1] + ws[2] + ws[3];
    float nrm = sqrtf(tot);
    float4 o4 = make_float4(tf32_round(v.x / nrm), tf32_round(v.y / nrm),
                            tf32_round(v.z / nrm), tf32_round(v.w / nrm));
    ((float4*)g_fn)[(size_t)i * (D / 4) + tid] = o4;
}

// ---------------- 3) symmetric tensor-core GEMM + exp, cp.async 2-stage ------
#define KT 32
#define NKT (D / KT)
__global__ __launch_bounds__(256) void gemm_mma_sym_kernel() {
    extern __shared__ float dyn[];
    float (*As)[128][36] = (float(*)[128][36])dyn;                 // 2 stages
    float (*Bs)[128][36] = (float(*)[128][36])(dyn + 2 * 128 * 36);
    int* permA = (int*)(dyn + 4 * 128 * 36);
    int* permB = permA + 128;

    int tid = threadIdx.x;
    int lane = tid & 31, wid = tid >> 5;
    int warp_m = wid & 3;    // 4 warps over 128 rows (32 each)
    int warp_n = wid >> 2;   // 2 warps over 128 cols (64 each)

    int bi = 0, bj = 0;
    {
        int r = blockIdx.x;
        #pragma unroll 1
        for (int b = 0; b < 32; b++) {
            int cnt = 32 - b;
            if (r < cnt) { bi = b; bj = b + r; break; }
            r -= cnt;
        }
    }
    if (tid < 128) permA[tid] = g_perm[bi * 128 + tid];
    else           permB[tid - 128] = g_perm[bj * 128 + (tid - 128)];
    __syncthreads();

    int lrow[4], lc4[4];
    #pragma unroll
    for (int l = 0; l < 4; l++) {
        int j = tid + l * 256;
        lrow[l] = j >> 3;
        lc4[l]  = (j & 7) * 4;
    }

    float acc[2][8][4];
    #pragma unroll
    for (int mf = 0; mf < 2; mf++)
        #pragma unroll
        for (int nf = 0; nf < 8; nf++)
            #pragma unroll
            for (int r = 0; r < 4; r++) acc[mf][nf][r] = 0.0f;

    // prefetch tile 0 into stage 0
    #pragma unroll
    for (int l = 0; l < 4; l++) {
        unsigned da = (unsigned)__cvta_generic_to_shared(&As[0][lrow[l]][lc4[l]]);
        asm volatile("cp.async.cg.shared.global [%0], [%1], 16;\n"
                     :: "r"(da), "l"(&g_fn[(size_t)permA[lrow[l]] * D + lc4[l]]));
        unsigned db = (unsigned)__cvta_generic_to_shared(&Bs[0][lrow[l]][lc4[l]]);
        asm volatile("cp.async.cg.shared.global [%0], [%1], 16;\n"
                     :: "r"(db), "l"(&g_fn[(size_t)permB[lrow[l]] * D + lc4[l]]));
    }
    asm volatile("cp.async.commit_group;\n");

    int stage = 0;
    for (int ki = 0; ki < NKT; ki++) {
        asm volatile("cp.async.wait_group 0;\n");
        __syncthreads();
        if (ki + 1 < NKT) {
            int kt = (ki + 1) * KT;
            int ns = stage ^ 1;
            #pragma unroll
            for (int l = 0; l < 4; l++) {
                unsigned da = (unsigned)__cvta_generic_to_shared(&As[ns][lrow[l]][lc4[l]]);
                asm volatile("cp.async.cg.shared.global [%0], [%1], 16;\n"
                             :: "r"(da), "l"(&g_fn[(size_t)permA[lrow[l]] * D + kt + lc4[l]]));
                unsigned db = (unsigned)__cvta_generic_to_shared(&Bs[ns][lrow[l]][lc4[l]]);
                asm volatile("cp.async.cg.shared.global [%0], [%1], 16;\n"
                             :: "r"(db), "l"(&g_fn[(size_t)permB[lrow[l]] * D + kt + lc4[l]]));
            }
            asm volatile("cp.async.commit_group;\n");
        }
        #pragma unroll
        for (int ks = 0; ks < 4; ks++) {
            int k0 = ks * 8 + (lane & 3);
            unsigned a[2][4], b[8][2];
            #pragma unroll
            for (int mf = 0; mf < 2; mf++) {
                int m0 = warp_m * 32 + mf * 16 + (lane >> 2);
                a[mf][0] = __float_as_uint(As[stage][m0][k0]);
                a[mf][1] = __float_as_uint(As[stage][m0 + 8][k0]);
                a[mf][2] = __float_as_uint(As[stage][m0][k0 + 4]);
                a[mf][3] = __float_as_uint(As[stage][m0 + 8][k0 + 4]);
            }
            #pragma unroll
            for (int nf = 0; nf < 8; nf++) {
                int n0 = warp_n * 64 + nf * 8 + (lane >> 2);
                b[nf][0] = __float_as_uint(Bs[stage][n0][k0]);
                b[nf][1] = __float_as_uint(Bs[stage][n0][k0 + 4]);
            }
            #pragma unroll
            for (int mf = 0; mf < 2; mf++)
                #pragma unroll
                for (int nf = 0; nf < 8; nf++)
                    mma_tf32(acc[mf][nf], a[mf], b[nf]);
        }
        __syncthreads();
        stage ^= 1;
    }

    // exp epilogue in registers
    #pragma unroll
    for (int mf = 0; mf < 2; mf++)
        #pragma unroll
        for (int nf = 0; nf < 8; nf++)
            #pragma unroll
            for (int r = 0; r < 4; r++)
                acc[mf][nf][r] = expf(acc[mf][nf][r] / 0.07f);

    // direct writes
    #pragma unroll
    for (int mf = 0; mf < 2; mf++) {
        #pragma unroll
        for (int r = 0; r < 4; r++) {
            int row_local = warp_m * 32 + mf * 16 + (lane >> 2) + ((r >> 1) ? 8 : 0);
            int gq1 = bi * 128 + row_local;
            #pragma unroll
            for (int nf = 0; nf < 8; nf++) {
                int col_local = warp_n * 64 + nf * 8 + (lane & 3) * 2 + (r & 1);
                g_sims[(size_t)gq1 * N + bj * 128 + col_local] = acc[mf][nf][r];
            }
        }
    }

    // mirror write via transpose bounce
    if (bi != bj) {
        float (*stg)[129] = (float(*)[129])dyn;
        #pragma unroll 1
        for (int cc = 0; cc < 4; cc++) {
            __syncthreads();
            if (warp_m == cc) {
                #pragma unroll
                for (int mf = 0; mf < 2; mf++) {
                    #pragma unroll
                    for (int r = 0; r < 4; r++) {
                        int rr = mf * 16 + (lane >> 2) + ((r >> 1) ? 8 : 0);
                        #pragma unroll
                        for (int nf = 0; nf < 8; nf++) {
                            int col_local = warp_n * 64 + nf * 8 + (lane & 3) * 2 + (r & 1);
                            stg[rr][col_local] = acc[mf][nf][r];
                        }
                    }
                }
            }
            __syncthreads();
            for (int j = tid; j < 32 * 128; j += 256) {
                int rr = j & 31, cp = j >> 5;
                g_sims[(size_t)(bj * 128 + cp) * N + bi * 128 + cc * 32 + rr] = stg[rr][cp];
            }
        }
    }
}

// ---------------- 4) fused per-row prefix scan + loss terms (R11 form) -------
__global__ __launch_bounds__(512) void scan_terms_kernel() {
    extern __shared__ char dsm[];
    double* spref = (double*)dsm;                    // 32 KB
    float*  lsh   = (float*)(dsm + 32768);           // 16 KB
    double* red   = (double*)(dsm + 32768 + 16384);  // 4 KB
    __shared__ double warpsum[16];

    int q1 = blockIdx.x, tid = threadIdx.x;  // 512 threads
    const float* __restrict__ row = g_sims + (size_t)q1 * N;

    for (int p = tid; p < N; p += 512) lsh[p] = g_ls[p];

    // ---- prefix scan (bitwise-same arithmetic as R9-R12) -------------------
    const float4* r4 = (const float4*)row;
    float4 v0 = r4[tid * 2 + 0];
    float4 v1 = r4[tid * 2 + 1];
    double loc[8];
    double s = 0.0;
    s += (double)v0.x; loc[0] = s;
    s += (double)v0.y; loc[1] = s;
    s += (double)v0.z; loc[2] = s;
    s += (double)v0.w; loc[3] = s;
    s += (double)v1.x; loc[4] = s;
    s += (double)v1.y; loc[5] = s;
    s += (double)v1.z; loc[6] = s;
    s += (double)v1.w; loc[7] = s;

    double ws = s;
    #pragma unroll
    for (int o = 1; o < 32; o <<= 1) {
        double v = __shfl_up_sync(0xffffffffu, ws, o);
        if ((tid & 31) >= o) ws += v;
    }
    if ((tid & 31) == 31) warpsum[tid >> 5] = ws;
    __syncthreads();
    if (tid < 16) {
        double w = warpsum[tid];
        #pragma unroll
        for (int o = 1; o < 16; o <<= 1) {
            double v = __shfl_up_sync(0x0000ffffu, w, o);
            if (tid >= o) w += v;
        }
        warpsum[tid] = w;
    }
    __syncthreads();
    double offset = ws - s;  // exclusive within warp
    if (tid >= 32) offset += warpsum[(tid >> 5) - 1];
    int base = tid * 8;
    #pragma unroll
    for (int k = 0; k < 8; k++) spref[base + k] = loc[k] + offset;
    __syncthreads();

    // ---- terms: strided p, uniform binary searches (R11 exact code) --------
    const float li = lsh[q1];
    const int ipos = q1;
    const double selfsim = (double)__ldg(&row[ipos]);
    const double St = spref[N - 1] - selfsim;
    const double qt = rint(St * 8.0);

    double acc = 0.0;
    for (int p = tid; p < N; p += 512) {
        if (p == ipos) continue;  // diagonal mask
        float t = fabsf(li - lsh[p]);
        int a, b;
        if (p > ipos) {
            b = p;
            while (b + 1 < N && fabsf(li - lsh[b + 1]) <= t) b++;  // tie extent
            int lo = 0, hi = ipos;
            while (lo < hi) {
                int mid = (lo + hi) >> 1;
                if (fabsf(li - lsh[mid]) <= t) hi = mid; else lo = mid + 1;
            }
            a = lo;
        } else {
            a = p;
            while (a > 0 && fabsf(li - lsh[a - 1]) <= t) a--;  // tie extent
            int lo = ipos, hi = N - 1;
            while (lo < hi) {
                int mid = (lo + hi + 1) >> 1;
                if (fabsf(li - lsh[mid]) <= t) lo = mid; else hi = mid - 1;
            }
            b = lo;
        }
        double W  = spref[b] - (a > 0 ? spref[a - 1] : 0.0);
        double Sm = W - selfsim;
        double den = (qt - rint(Sm * 8.0)) * 0.125;
        if (den > 0.0) {
            acc += (double)__ldg(&row[p]) / den;
        }
    }

    red[tid] = acc;
    __syncthreads();
    for (int o = 256; o > 0; o >>= 1) {
        if (tid < o) red[tid] += red[tid + o];
        __syncthreads();
    }
    if (tid == 0) g_loss[q1] = red[0] / (double)(N - 1);
}

// ---------------- 5) deterministic final reduction ---------------------------
__global__ void final_reduce_kernel(float* __restrict__ out) {
    __shared__ double red[512];
    int tid = threadIdx.x;
    double s = 0.0;
    for (int k = tid; k < N; k += 512) s += g_loss[k];
    red[tid] = s;
    __syncthreads();
    for (int o = 256; o > 0; o >>= 1) {
        if (tid < o) red[tid] += red[tid + o];
        __syncthreads();
    }
    if (tid == 0) out[0] = (float)(red[0] / (double)N);
}

// ---------------- launcher ----------------------------------------------------
extern "C" void kernel_launch(void* const* d_in, const int* in_sizes, int n_in,
                              void* d_out, int out_size) {
    const float* features = (const float*)d_in[0];
    const float* labels   = (const float*)d_in[1];
    float* out = (float*)d_out;

    cudaFuncSetAttribute(gemm_mma_sym_kernel,
                         cudaFuncAttributeMaxDynamicSharedMemorySize, 74752);
    cudaFuncSetAttribute(scan_terms_kernel,
                         cudaFuncAttributeMaxDynamicSharedMemorySize, 53248);

    sort_kernel<<<1, 1024>>>(labels);
    norm_kernel<<<N, 128>>>(features);
    gemm_mma_sym_kernel<<<528, 256, 74752>>>();
    scan_terms_kernel<<<N, 512, 53248>>>();
    final_reduce_kernel<<<1, 512>>>(out);
}

// round 15
// speedup vs baseline: 1.5857x; 1.0590x over previous
#include <cuda_runtime.h>
#include <math.h>

#define N 4096
#define D 512

// ---------------- scratch (static __device__, per harness rules) -------------
__device__ float  g_fn[(size_t)N * D];      // normalized features, TF32-rounded
__device__ float  g_sims[(size_t)N * N];    // sims2[q1][q2], both axes label-sorted
__device__ float  g_ls[N];                  // sorted labels
__device__ int    g_perm[N];                // perm[q] = original index
__device__ int    g_ipos[N];                // ipos[i]  = position of i in sorted order
__device__ double g_loss[N];                // per-row losses

__device__ __forceinline__ float tf32_round(float x) {
    unsigned r;
    asm("cvt.rna.tf32.f32 %0, %1;" : "=r"(r) : "f"(x));
    return __uint_as_float(r);
}

// m16n8k8 TF32 MMA, fp32 accumulate
__device__ __forceinline__ void mma_tf32(float* c, const unsigned* a, const unsigned* b) {
    asm volatile(
        "mma.sync.aligned.m16n8k8.row.col.f32.tf32.tf32.f32 "
        "{%0,%1,%2,%3}, {%4,%5,%6,%7}, {%8,%9}, {%0,%1,%2,%3};\n"
        : "+f"(c[0]), "+f"(c[1]), "+f"(c[2]), "+f"(c[3])
        : "r"(a[0]), "r"(a[1]), "r"(a[2]), "r"(a[3]), "r"(b[0]), "r"(b[1]));
}

// ---------------- 1) bitonic sort of labels (single block) -------------------
__global__ void sort_kernel(const float* __restrict__ labels) {
    __shared__ float key[N];
    __shared__ int   idx[N];
    int tid = threadIdx.x;  // 1024 threads
    for (int p = tid; p < N; p += 1024) { key[p] = labels[p]; idx[p] = p; }
    __syncthreads();
    for (int k = 2; k <= N; k <<= 1) {
        for (int j = k >> 1; j > 0; j >>= 1) {
            for (int p = tid; p < N; p += 1024) {
                int q = p ^ j;
                if (q > p) {
                    bool up = ((p & k) == 0);
                    float a = key[p], b = key[q];
                    bool swap = up ? (a > b || (a == b && idx[p] > idx[q]))
                                   : (a < b || (a == b && idx[p] < idx[q]));
                    if (swap) {
                        key[p] = b; key[q] = a;
                        int t2 = idx[p]; idx[p] = idx[q]; idx[q] = t2;
                    }
                }
            }
            __syncthreads();
        }
    }
    for (int p = tid; p < N; p += 1024) {
        g_ls[p] = key[p];
        g_perm[p] = idx[p];
        g_ipos[idx[p]] = p;
    }
}

// ---------------- 2) row normalization, output rounded to TF32 ---------------
__global__ void norm_kernel(const float* __restrict__ X) {
    int i = blockIdx.x, tid = threadIdx.x;  // 128 threads, 512 elems
    const float4* xr = (const float4*)(X + (size_t)i * D);
    float4 v = xr[tid];
    float ss = v.x * v.x + v.y * v.y + v.z * v.z + v.w * v.w;
    #pragma unroll
    for (int o = 16; o > 0; o >>= 1) ss += __shfl_xor_sync(0xffffffffu, ss, o);
    __shared__ float ws[4];
    if ((tid & 31) == 0) ws[tid >> 5] = ss;
    __syncthreads();
    float tot = ws[0] + ws[1] + ws[2] + ws[3];
    float nrm = sqrtf(tot);
    float4 o4 = make_float4(tf32_round(v.x / nrm), tf32_round(v.y / nrm),
                            tf32_round(v.z / nrm), tf32_round(v.w / nrm));
    ((float4*)g_fn)[(size_t)i * (D / 4) + tid] = o4;
}

// ---------------- 3) symmetric tensor-core GEMM + exp, cp.async 2-stage ------
#define KT 32
#define NKT (D / KT)
__global__ __launch_bounds__(256) void gemm_mma_sym_kernel() {
    extern __shared__ float dyn[];
    float (*As)[128][36] = (float(*)[128][36])dyn;                 // 2 stages
    float (*Bs)[128][36] = (float(*)[128][36])(dyn + 2 * 128 * 36);
    int* permA = (int*)(dyn + 4 * 128 * 36);
    int* permB = permA + 128;

    int tid = threadIdx.x;
    int lane = tid & 31, wid = tid >> 5;
    int warp_m = wid & 3;
    int warp_n = wid >> 2;

    int bi = 0, bj = 0;
    {
        int r = blockIdx.x;
        #pragma unroll 1
        for (int b = 0; b < 32; b++) {
            int cnt = 32 - b;
            if (r < cnt) { bi = b; bj = b + r; break; }
            r -= cnt;
        }
    }
    if (tid < 128) permA[tid] = g_perm[bi * 128 + tid];
    else           permB[tid - 128] = g_perm[bj * 128 + (tid - 128)];
    __syncthreads();

    int lrow[4], lc4[4];
    #pragma unroll
    for (int l = 0; l < 4; l++) {
        int j = tid + l * 256;
        lrow[l] = j >> 3;
        lc4[l]  = (j & 7) * 4;
    }

    float acc[2][8][4];
    #pragma unroll
    for (int mf = 0; mf < 2; mf++)
        #pragma unroll
        for (int nf = 0; nf < 8; nf++)
            #pragma unroll
            for (int r = 0; r < 4; r++) acc[mf][nf][r] = 0.0f;

    #pragma unroll
    for (int l = 0; l < 4; l++) {
        unsigned da = (unsigned)__cvta_generic_to_shared(&As[0][lrow[l]][lc4[l]]);
        asm volatile("cp.async.cg.shared.global [%0], [%1], 16;\n"
                     :: "r"(da), "l"(&g_fn[(size_t)permA[lrow[l]] * D + lc4[l]]));
        unsigned db = (unsigned)__cvta_generic_to_shared(&Bs[0][lrow[l]][lc4[l]]);
        asm volatile("cp.async.cg.shared.global [%0], [%1], 16;\n"
                     :: "r"(db), "l"(&g_fn[(size_t)permB[lrow[l]] * D + lc4[l]]));
    }
    asm volatile("cp.async.commit_group;\n");

    int stage = 0;
    for (int ki = 0; ki < NKT; ki++) {
        asm volatile("cp.async.wait_group 0;\n");
        __syncthreads();
        if (ki + 1 < NKT) {
            int kt = (ki + 1) * KT;
            int ns = stage ^ 1;
            #pragma unroll
            for (int l = 0; l < 4; l++) {
                unsigned da = (unsigned)__cvta_generic_to_shared(&As[ns][lrow[l]][lc4[l]]);
                asm volatile("cp.async.cg.shared.global [%0], [%1], 16;\n"
                             :: "r"(da), "l"(&g_fn[(size_t)permA[lrow[l]] * D + kt + lc4[l]]));
                unsigned db = (unsigned)__cvta_generic_to_shared(&Bs[ns][lrow[l]][lc4[l]]);
                asm volatile("cp.async.cg.shared.global [%0], [%1], 16;\n"
                             :: "r"(db), "l"(&g_fn[(size_t)permB[lrow[l]] * D + kt + lc4[l]]));
            }
            asm volatile("cp.async.commit_group;\n");
        }
        #pragma unroll
        for (int ks = 0; ks < 4; ks++) {
            int k0 = ks * 8 + (lane & 3);
            unsigned a[2][4], b[8][2];
            #pragma unroll
            for (int mf = 0; mf < 2; mf++) {
                int m0 = warp_m * 32 + mf * 16 + (lane >> 2);
                a[mf][0] = __float_as_uint(As[stage][m0][k0]);
                a[mf][1] = __float_as_uint(As[stage][m0 + 8][k0]);
                a[mf][2] = __float_as_uint(As[stage][m0][k0 + 4]);
                a[mf][3] = __float_as_uint(As[stage][m0 + 8][k0 + 4]);
            }
            #pragma unroll
            for (int nf = 0; nf < 8; nf++) {
                int n0 = warp_n * 64 + nf * 8 + (lane >> 2);
                b[nf][0] = __float_as_uint(Bs[stage][n0][k0]);
                b[nf][1] = __float_as_uint(Bs[stage][n0][k0 + 4]);
            }
            #pragma unroll
            for (int mf = 0; mf < 2; mf++)
                #pragma unroll
                for (int nf = 0; nf < 8; nf++)
                    mma_tf32(acc[mf][nf], a[mf], b[nf]);
        }
        __syncthreads();
        stage ^= 1;
    }

    #pragma unroll
    for (int mf = 0; mf < 2; mf++)
        #pragma unroll
        for (int nf = 0; nf < 8; nf++)
            #pragma unroll
            for (int r = 0; r < 4; r++)
                acc[mf][nf][r] = expf(acc[mf][nf][r] / 0.07f);

    #pragma unroll
    for (int mf = 0; mf < 2; mf++) {
        #pragma unroll
        for (int r = 0; r < 4; r++) {
            int row_local = warp_m * 32 + mf * 16 + (lane >> 2) + ((r >> 1) ? 8 : 0);
            int gq1 = bi * 128 + row_local;
            #pragma unroll
            for (int nf = 0; nf < 8; nf++) {
                int col_local = warp_n * 64 + nf * 8 + (lane & 3) * 2 + (r & 1);
                g_sims[(size_t)gq1 * N + bj * 128 + col_local] = acc[mf][nf][r];
            }
        }
    }

    if (bi != bj) {
        float (*stg)[129] = (float(*)[129])dyn;
        #pragma unroll 1
        for (int cc = 0; cc < 4; cc++) {
            __syncthreads();
            if (warp_m == cc) {
                #pragma unroll
                for (int mf = 0; mf < 2; mf++) {
                    #pragma unroll
                    for (int r = 0; r < 4; r++) {
                        int rr = mf * 16 + (lane >> 2) + ((r >> 1) ? 8 : 0);
                        #pragma unroll
                        for (int nf = 0; nf < 8; nf++) {
                            int col_local = warp_n * 64 + nf * 8 + (lane & 3) * 2 + (r & 1);
                            stg[rr][col_local] = acc[mf][nf][r];
                        }
                    }
                }
            }
            __syncthreads();
            for (int j = tid; j < 32 * 128; j += 256) {
                int rr = j & 31, cp = j >> 5;
                g_sims[(size_t)(bj * 128 + cp) * N + bi * 128 + cc * 32 + rr] = stg[rr][cp];
            }
        }
    }
}

// ---------------- 4) fused scan + merge-path loss terms ----------------------
// Window ends per p are a single merge of the left/right distance sequences
// (each sorted outward from ipos). Merge-path: each thread diagonal-searches
// once, then walks exactly 8 events -> balanced lanes. den values are bitwise
// identical to the per-p binary-search version (same <= predicates, ties via
// Y-first rule + equal-value lookaheads). Division fp32 (den float-exact).
#define DISTL(i2) fabsf(li - lsh[ipos - 1 - (i2)])   /* Y[i2], i2 in [0,Lc) */
#define DISTR(j)  fabsf(li - lsh[ipos + 1 + (j)])    /* X[j],  j  in [0,Rc) */
__global__ __launch_bounds__(512) void scan_terms_kernel() {
    extern __shared__ char dsm[];
    double* spref = (double*)dsm;                    // 32 KB
    float*  lsh   = (float*)(dsm + 32768);           // 16 KB
    double* red   = (double*)(dsm + 32768 + 16384);  // 4 KB
    __shared__ double warpsum[16];

    int q1 = blockIdx.x, tid = threadIdx.x;  // 512 threads
    const float* __restrict__ row = g_sims + (size_t)q1 * N;

    for (int p = tid; p < N; p += 512) lsh[p] = g_ls[p];

    // ---- prefix scan (bitwise-same arithmetic as R9-R13) -------------------
    const float4* r4 = (const float4*)row;
    float4 v0 = r4[tid * 2 + 0];
    float4 v1 = r4[tid * 2 + 1];
    double loc[8];
    double s = 0.0;
    s += (double)v0.x; loc[0] = s;
    s += (double)v0.y; loc[1] = s;
    s += (double)v0.z; loc[2] = s;
    s += (double)v0.w; loc[3] = s;
    s += (double)v1.x; loc[4] = s;
    s += (double)v1.y; loc[5] = s;
    s += (double)v1.z; loc[6] = s;
    s += (double)v1.w; loc[7] = s;

    double ws = s;
    #pragma unroll
    for (int o = 1; o < 32; o <<= 1) {
        double v = __shfl_up_sync(0xffffffffu, ws, o);
        if ((tid & 31) >= o) ws += v;
    }
    if ((tid & 31) == 31) warpsum[tid >> 5] = ws;
    __syncthreads();
    if (tid < 16) {
        double w = warpsum[tid];
        #pragma unroll
        for (int o = 1; o < 16; o <<= 1) {
            double v = __shfl_up_sync(0x0000ffffu, w, o);
            if (tid >= o) w += v;
        }
        warpsum[tid] = w;
    }
    __syncthreads();
    double offset = ws - s;  // exclusive within warp
    if (tid >= 32) offset += warpsum[(tid >> 5) - 1];
    int base = tid * 8;
    #pragma unroll
    for (int k = 0; k < 8; k++) spref[base + k] = loc[k] + offset;
    __syncthreads();

    // ---- merge-path terms --------------------------------------------------
    const float li = lsh[q1];
    const int ipos = q1;
    const double selfsim = (double)__ldg(&row[ipos]);
    const double St = spref[N - 1] - selfsim;
    const double qt = rint(St * 8.0);

    const int Lc = ipos;          // left sequence length
    const int Rc = N - 1 - ipos;  // right sequence length
    const int M  = N - 1;         // total merge events
    const float FINF = __int_as_float(0x7f800000);

    double acc = 0.0;
    int k0 = tid * 8;
    if (k0 < M) {
        int kend = k0 + 8 < M ? k0 + 8 : M;
        // diagonal search: smallest iY with P(iY) (Y-first tie rule)
        int lo = k0 - Rc; if (lo < 0) lo = 0;
        int hi = k0 < Lc ? k0 : Lc;
        while (lo < hi) {
            int mid = (lo + hi) >> 1;
            int iXc = k0 - mid;
            bool P = (iXc == 0) || (mid >= Lc) || (DISTR(iXc - 1) < DISTL(mid));
            if (P) hi = mid; else lo = mid + 1;
        }
        int iY = lo, iX = k0 - lo;

        float dX = (iX < Rc) ? DISTR(iX) : FINF;
        float dY = (iY < Lc) ? DISTL(iY) : FINF;
        for (int k = k0; k < kend; k++) {
            bool takeY = (iY < Lc) && (dY <= dX);
            int a, b, p;
            if (takeY) {
                float t = dY; iY++;
                p = ipos - iY;
                int nl = iY; while (nl < Lc && DISTL(nl) <= t) nl++;  // Y ties
                int nr = iX; while (nr < Rc && DISTR(nr) <= t) nr++;  // X ties (== t)
                a = ipos - nl; b = ipos + nr;
                dY = (iY < Lc) ? DISTL(iY) : FINF;
            } else {
                float t = dX; iX++;
                p = ipos + iX;
                int nr = iX; while (nr < Rc && DISTR(nr) <= t) nr++;  // X ties
                a = ipos - iY; b = ipos + nr;    // all Y <= t already consumed
                dX = (iX < Rc) ? DISTR(iX) : FINF;
            }
            double W = spref[b] - (a > 0 ? spref[a - 1] : 0.0);
            double den = (qt - rint((W - selfsim) * 8.0)) * 0.125;
            if (den > 0.0) {
                acc += (double)__fdiv_rn(__ldg(&row[p]), (float)den);
            }
        }
    }

    red[tid] = acc;
    __syncthreads();
    for (int o = 256; o > 0; o >>= 1) {
        if (tid < o) red[tid] += red[tid + o];
        __syncthreads();
    }
    if (tid == 0) g_loss[q1] = red[0] / (double)(N - 1);
}

// ---------------- 5) deterministic final reduction ---------------------------
__global__ void final_reduce_kernel(float* __restrict__ out) {
    __shared__ double red[512];
    int tid = threadIdx.x;
    double s = 0.0;
    for (int k = tid; k < N; k += 512) s += g_loss[k];
    red[tid] = s;
    __syncthreads();
    for (int o = 256; o > 0; o >>= 1) {
        if (tid < o) red[tid] += red[tid + o];
        __syncthreads();
    }
    if (tid == 0) out[0] = (float)(red[0] / (double)N);
}

// ---------------- launcher ----------------------------------------------------
extern "C" void kernel_launch(void* const* d_in, const int* in_sizes, int n_in,
                              void* d_out, int out_size) {
    const float* features = (const float*)d_in[0];
    const float* labels   = (const float*)d_in[1];
    float* out = (float*)d_out;

    cudaFuncSetAttribute(gemm_mma_sym_kernel,
                         cudaFuncAttributeMaxDynamicSharedMemorySize, 74752);
    cudaFuncSetAttribute(scan_terms_kernel,
                         cudaFuncAttributeMaxDynamicSharedMemorySize, 53248);

    sort_kernel<<<1, 1024>>>(labels);
    norm_kernel<<<N, 128>>>(features);
    gemm_mma_sym_kernel<<<528, 256, 74752>>>();
    scan_terms_kernel<<<N, 512, 53248>>>();
    final_reduce_kernel<<<1, 512>>>(out);
}